// round 4
// baseline (speedup 1.0000x reference)
#include <cuda_runtime.h>
#include <cstddef>

#define NNODES 100000
#define NE     200000
#define DD     300
#define DD2    600
#define M_PAD  100096   // 128 * 782

// ---------------- scratch (static device globals; no runtime allocation) ----
__device__ float g_agg[(size_t)M_PAD * DD];     // aggregated messages (padded rows are zero)
__device__ float g_h1[(size_t)M_PAD * DD2];     // hidden after GEMM1+ReLU
__device__ float g_combo[18 * DD];              // all 6*3 edge-embedding rows (+biases)
__device__ float g_stats[2 * DD];               // per-column sum, sumsq
__device__ float g_ss[2 * DD];                  // per-column scale, shift

// ---------------- small init kernels ---------------------------------------
__global__ void combo_init_kernel(const float* __restrict__ w0, const float* __restrict__ b0,
                                  const float* __restrict__ w1, const float* __restrict__ b1)
{
    int b = blockIdx.x;
    if (b < 18) {
        int i0 = b / 3, i1 = b % 3;
        for (int d = threadIdx.x; d < DD; d += blockDim.x)
            g_combo[b * DD + d] = w0[i0 * DD + d] + b0[d] + w1[i1 * DD + d] + b1[d];
    } else {
        for (int d = threadIdx.x; d < 2 * DD; d += blockDim.x)
            g_stats[d] = 0.f;
    }
}

__global__ void zero_agg_kernel()
{
    const size_t n4 = (size_t)M_PAD * DD / 4;
    float4 z = make_float4(0.f, 0.f, 0.f, 0.f);
    float4* p = (float4*)g_agg;
    for (size_t i = (size_t)blockIdx.x * blockDim.x + threadIdx.x; i < n4;
         i += (size_t)gridDim.x * blockDim.x)
        p[i] = z;
}

// ---------------- edge scatter: agg[dst] += node_feats[src] + combo --------
__global__ void scatter_kernel(const float* __restrict__ nf, const int* __restrict__ src,
                               const int* __restrict__ dst, const int* __restrict__ f0,
                               const int* __restrict__ f1)
{
    int e = (blockIdx.x * blockDim.x + threadIdx.x) >> 5;  // one warp per edge
    int lane = threadIdx.x & 31;
    if (e >= NE) return;
    int s = __ldg(&src[e]);
    int t = __ldg(&dst[e]);
    int c = __ldg(&f0[e]) * 3 + __ldg(&f1[e]);
    const float4* nrow = (const float4*)(nf + (size_t)s * DD);
    const float4* crow = (const float4*)(g_combo + c * DD);
    float* orow = g_agg + (size_t)t * DD;
    for (int j = lane; j < DD / 4; j += 32) {
        float4 a = nrow[j];
        float4 b = crow[j];
        atomicAdd(orow + j * 4 + 0, a.x + b.x);
        atomicAdd(orow + j * 4 + 1, a.y + b.y);
        atomicAdd(orow + j * 4 + 2, a.z + b.z);
        atomicAdd(orow + j * 4 + 3, a.w + b.w);
    }
}

// ---------------- fp32 register-blocked GEMM (fused bias / ReLU) ------------
// C[M_PAD, NCOLS] = A[M_PAD, KDIM] * B[KDIM, NCOLS] + bias, optional ReLU.
template<int KDIM, int NCOLS, int BM, int BN, int BK, int TM, int TN, bool RELU, bool GUARD>
__global__ __launch_bounds__((BM / TM) * (BN / TN))
void sgemm_kernel(const float* __restrict__ A, const float* __restrict__ B,
                  const float* __restrict__ bias, float* __restrict__ C)
{
    constexpr int TX  = BN / TN;     // 15
    constexpr int TY  = BM / TM;     // 16
    constexpr int NT  = TX * TY;     // 240
    constexpr int AK4 = BK / 4;
    constexpr int BN4 = BN / 4;

    __shared__ float As[BK][BM + 4]; // transposed A tile (+4 pad: kills 20-way store conflicts)
    __shared__ float Bs[BK][BN];

    const int tid = threadIdx.x;
    const int tx = tid % TX;
    const int ty = tid / TX;
    const int rowBase = blockIdx.y * BM;
    const int colBase = blockIdx.x * BN;

    float acc[TM * TN];
#pragma unroll
    for (int i = 0; i < TM * TN; ++i) acc[i] = 0.f;

    for (int kt = 0; kt < KDIM; kt += BK) {
        // A tile: float4 global loads, store transposed
        for (int idx = tid; idx < BM * AK4; idx += NT) {
            int row = idx / AK4;
            int k4  = idx % AK4;
            float4 v = *(const float4*)&A[(size_t)(rowBase + row) * KDIM + kt + k4 * 4];
            As[k4 * 4 + 0][row] = v.x;
            As[k4 * 4 + 1][row] = v.y;
            As[k4 * 4 + 2][row] = v.z;
            As[k4 * 4 + 3][row] = v.w;
        }
        // B tile: fully coalesced float4
        for (int idx = tid; idx < BK * BN4; idx += NT) {
            int row = idx / BN4;
            int c4  = idx % BN4;
            *(float4*)&Bs[row][c4 * 4] =
                *(const float4*)&B[(size_t)(kt + row) * NCOLS + colBase + c4 * 4];
        }
        __syncthreads();

#pragma unroll
        for (int k = 0; k < BK; ++k) {
            float4 af[TM / 4], bf[TN / 4];
#pragma unroll
            for (int i = 0; i < TM / 4; ++i) af[i] = *(const float4*)&As[k][ty * TM + i * 4];
#pragma unroll
            for (int i = 0; i < TN / 4; ++i) bf[i] = *(const float4*)&Bs[k][tx * TN + i * 4];
            const float* a = (const float*)af;
            const float* b = (const float*)bf;
#pragma unroll
            for (int m = 0; m < TM; ++m)
#pragma unroll
                for (int n = 0; n < TN; ++n)
                    acc[m * TN + n] = fmaf(a[m], b[n], acc[m * TN + n]);
        }
        __syncthreads();
    }

#pragma unroll
    for (int m = 0; m < TM; ++m) {
        int row = rowBase + ty * TM + m;
        if (GUARD && row >= NNODES) continue;
#pragma unroll
        for (int n4 = 0; n4 < TN / 4; ++n4) {
            int col = colBase + tx * TN + n4 * 4;
            float4 v;
            v.x = acc[m * TN + n4 * 4 + 0] + bias[col + 0];
            v.y = acc[m * TN + n4 * 4 + 1] + bias[col + 1];
            v.z = acc[m * TN + n4 * 4 + 2] + bias[col + 2];
            v.w = acc[m * TN + n4 * 4 + 3] + bias[col + 3];
            if (RELU) {
                v.x = fmaxf(v.x, 0.f); v.y = fmaxf(v.y, 0.f);
                v.z = fmaxf(v.z, 0.f); v.w = fmaxf(v.w, 0.f);
            }
            *(float4*)&C[(size_t)row * NCOLS + col] = v;
        }
    }
}

// ---------------- BatchNorm --------------------------------------------------
__global__ void colstats_kernel(const float* __restrict__ X)
{
    int c = threadIdx.x;               // blockDim = 300, one column per thread
    int r0 = blockIdx.x * 250;
    int r1 = min(r0 + 250, NNODES);
    float s = 0.f, q = 0.f;
    for (int r = r0; r < r1; ++r) {
        float v = X[(size_t)r * DD + c];
        s += v;
        q = fmaf(v, v, q);
    }
    atomicAdd(&g_stats[c], s);
    atomicAdd(&g_stats[DD + c], q);
}

__global__ void bn_finalize_kernel(const float* __restrict__ gamma, const float* __restrict__ beta)
{
    int c = threadIdx.x;
    float inv_n = 1.f / (float)NNODES;
    float mean = g_stats[c] * inv_n;
    float var  = g_stats[DD + c] * inv_n - mean * mean;
    float sc = gamma[c] * rsqrtf(var + 1e-5f);
    g_ss[c] = sc;
    g_ss[DD + c] = beta[c] - mean * sc;
}

__global__ void bn_apply_kernel(float* __restrict__ X)
{
    const size_t n4 = (size_t)NNODES * (DD / 4);
    float4* p = (float4*)X;
    for (size_t i = (size_t)blockIdx.x * blockDim.x + threadIdx.x; i < n4;
         i += (size_t)gridDim.x * blockDim.x) {
        int c4 = (int)(i % (DD / 4)) * 4;
        float4 sc = *(const float4*)&g_ss[c4];
        float4 sh = *(const float4*)&g_ss[DD + c4];
        float4 x = p[i];
        x.x = fmaf(x.x, sc.x, sh.x);
        x.y = fmaf(x.y, sc.y, sh.y);
        x.z = fmaf(x.z, sc.z, sh.z);
        x.w = fmaf(x.w, sc.w, sh.w);
        p[i] = x;
    }
}

// ---------------- launch -----------------------------------------------------
extern "C" void kernel_launch(void* const* d_in, const int* in_sizes, int n_in,
                              void* d_out, int out_size)
{
    const float* node_feats = (const float*)d_in[0];
    const int*   src        = (const int*)d_in[1];
    const int*   dst        = (const int*)d_in[2];
    const int*   f0         = (const int*)d_in[3];
    const int*   f1         = (const int*)d_in[4];
    const float* emb_w0     = (const float*)d_in[5];
    const float* emb_b0     = (const float*)d_in[6];
    const float* emb_w1     = (const float*)d_in[7];
    const float* emb_b1     = (const float*)d_in[8];
    const float* w1         = (const float*)d_in[9];
    const float* b1         = (const float*)d_in[10];
    const float* w2         = (const float*)d_in[11];
    const float* b2         = (const float*)d_in[12];
    const float* gamma      = (const float*)d_in[13];
    const float* beta       = (const float*)d_in[14];
    float* out = (float*)d_out;

    float* agg; cudaGetSymbolAddress((void**)&agg, g_agg);
    float* h1;  cudaGetSymbolAddress((void**)&h1, g_h1);

    combo_init_kernel<<<19, 128>>>(emb_w0, emb_b0, emb_w1, emb_b1);
    zero_agg_kernel<<<2048, 256>>>();
    scatter_kernel<<<NE * 32 / 256, 256>>>(node_feats, src, dst, f0, f1);

    // GEMM1: (M_PAD x 300) * (300 x 600) + b1, ReLU -> g_h1
    sgemm_kernel<DD, DD2, 128, 120, 20, 8, 8, true, false>
        <<<dim3(DD2 / 120, M_PAD / 128), 240>>>(agg, w1, b1, h1);

    // GEMM2: (M_PAD x 600) * (600 x 300) + b2 -> out (guard rows >= NNODES)
    sgemm_kernel<DD2, DD, 128, 60, 20, 8, 4, false, true>
        <<<dim3(DD / 60, M_PAD / 128), 240>>>(h1, w2, b2, out);

    colstats_kernel<<<400, 300>>>(out);
    bn_finalize_kernel<<<1, 300>>>(gamma, beta);
    bn_apply_kernel<<<2048, 256>>>(out);
}

// round 5
// speedup vs baseline: 1.0417x; 1.0417x over previous
#include <cuda_runtime.h>
#include <cstddef>

#define NNODES 100000
#define NE     200000
#define DD     300
#define DD2    600
#define M_PAD  100096   // 128 * 782

// ---------------- scratch (static device globals; no runtime allocation) ----
__device__ float g_agg[(size_t)M_PAD * DD];     // aggregated messages (padded rows are zero)
__device__ float g_h1[(size_t)M_PAD * DD2];     // hidden after GEMM1+ReLU
__device__ float g_combo[18 * DD];              // all 6*3 edge-embedding rows (+biases)
__device__ float g_stats[2 * DD];               // per-column sum, sumsq
__device__ float g_ss[2 * DD];                  // per-column scale, shift

// ---------------- packed f32x2 helpers --------------------------------------
__device__ __forceinline__ void ffma2(unsigned long long& acc,
                                      unsigned long long a, unsigned long long b)
{
    asm("fma.rn.f32x2 %0, %1, %2, %0;" : "+l"(acc) : "l"(a), "l"(b));
}

__device__ __forceinline__ unsigned long long dup_f32(float v)
{
    unsigned long long r;
    unsigned int u = __float_as_uint(v);
    asm("mov.b64 %0, {%1, %1};" : "=l"(r) : "r"(u));
    return r;
}

__device__ __forceinline__ float2 unpack2(unsigned long long v)
{
    float2 r;
    asm("mov.b64 {%0, %1}, %2;" : "=f"(r.x), "=f"(r.y) : "l"(v));
    return r;
}

// ---------------- small init kernels ---------------------------------------
__global__ void combo_init_kernel(const float* __restrict__ w0, const float* __restrict__ b0,
                                  const float* __restrict__ w1, const float* __restrict__ b1)
{
    int b = blockIdx.x;
    if (b < 18) {
        int i0 = b / 3, i1 = b % 3;
        for (int d = threadIdx.x; d < DD; d += blockDim.x)
            g_combo[b * DD + d] = w0[i0 * DD + d] + b0[d] + w1[i1 * DD + d] + b1[d];
    } else {
        for (int d = threadIdx.x; d < 2 * DD; d += blockDim.x)
            g_stats[d] = 0.f;
    }
}

__global__ void zero_agg_kernel()
{
    const size_t n4 = (size_t)M_PAD * DD / 4;
    float4 z = make_float4(0.f, 0.f, 0.f, 0.f);
    float4* p = (float4*)g_agg;
    for (size_t i = (size_t)blockIdx.x * blockDim.x + threadIdx.x; i < n4;
         i += (size_t)gridDim.x * blockDim.x)
        p[i] = z;
}

// ---------------- edge scatter: agg[dst] += node_feats[src] + combo --------
__global__ void scatter_kernel(const float* __restrict__ nf, const int* __restrict__ src,
                               const int* __restrict__ dst, const int* __restrict__ f0,
                               const int* __restrict__ f1)
{
    int e = (blockIdx.x * blockDim.x + threadIdx.x) >> 5;  // one warp per edge
    int lane = threadIdx.x & 31;
    if (e >= NE) return;
    int s = __ldg(&src[e]);
    int t = __ldg(&dst[e]);
    int c = __ldg(&f0[e]) * 3 + __ldg(&f1[e]);
    const float4* nrow = (const float4*)(nf + (size_t)s * DD);
    const float4* crow = (const float4*)(g_combo + c * DD);
    float* orow = g_agg + (size_t)t * DD;
    for (int j = lane; j < DD / 4; j += 32) {
        float4 a = nrow[j];
        float4 b = crow[j];
        atomicAdd(orow + j * 4 + 0, a.x + b.x);
        atomicAdd(orow + j * 4 + 1, a.y + b.y);
        atomicAdd(orow + j * 4 + 2, a.z + b.z);
        atomicAdd(orow + j * 4 + 3, a.w + b.w);
    }
}

// ---------------- fp32 GEMM with packed FFMA2 (fused bias / ReLU) -----------
// C[M_PAD, NCOLS] = A[M_PAD, KDIM] * B[KDIM, NCOLS] + bias, optional ReLU.
// Accumulators are packed pairs along m (fma.rn.f32x2): a-pairs come free from
// the transposed As tile; b values are duplicated into both 32-bit halves.
template<int KDIM, int NCOLS, int BM, int BN, int BK, int TM, int TN, bool RELU, bool GUARD>
__global__ __launch_bounds__((BM / TM) * (BN / TN))
void sgemm_kernel(const float* __restrict__ A, const float* __restrict__ B,
                  const float* __restrict__ bias, float* __restrict__ C)
{
    constexpr int TX  = BN / TN;
    constexpr int TY  = BM / TM;
    constexpr int NT  = TX * TY;
    constexpr int AK4 = BK / 4;
    constexpr int BN4 = BN / 4;
    constexpr int TMP = TM / 2;      // m-pairs

    __shared__ float As[BK][BM + 4]; // transposed A tile
    __shared__ float Bs[BK][BN];

    const int tid = threadIdx.x;
    const int tx = tid % TX;
    const int ty = tid / TX;
    const int rowBase = blockIdx.y * BM;
    const int colBase = blockIdx.x * BN;

    unsigned long long acc2[TMP * TN];
#pragma unroll
    for (int i = 0; i < TMP * TN; ++i) acc2[i] = 0ull;

    for (int kt = 0; kt < KDIM; kt += BK) {
        for (int idx = tid; idx < BM * AK4; idx += NT) {
            int row = idx / AK4;
            int k4  = idx % AK4;
            float4 v = *(const float4*)&A[(size_t)(rowBase + row) * KDIM + kt + k4 * 4];
            As[k4 * 4 + 0][row] = v.x;
            As[k4 * 4 + 1][row] = v.y;
            As[k4 * 4 + 2][row] = v.z;
            As[k4 * 4 + 3][row] = v.w;
        }
        for (int idx = tid; idx < BK * BN4; idx += NT) {
            int row = idx / BN4;
            int c4  = idx % BN4;
            *(float4*)&Bs[row][c4 * 4] =
                *(const float4*)&B[(size_t)(kt + row) * NCOLS + colBase + c4 * 4];
        }
        __syncthreads();

#pragma unroll
        for (int k = 0; k < BK; ++k) {
            float4 af[TM / 4], bf[TN / 4];
#pragma unroll
            for (int i = 0; i < TM / 4; ++i) af[i] = *(const float4*)&As[k][ty * TM + i * 4];
#pragma unroll
            for (int i = 0; i < TN / 4; ++i) bf[i] = *(const float4*)&Bs[k][tx * TN + i * 4];
            const unsigned long long* ap = (const unsigned long long*)af;  // (m, m+1) pairs
            const float* b = (const float*)bf;
            unsigned long long bb[TN];
#pragma unroll
            for (int n = 0; n < TN; ++n) bb[n] = dup_f32(b[n]);
#pragma unroll
            for (int p = 0; p < TMP; ++p)
#pragma unroll
                for (int n = 0; n < TN; ++n)
                    ffma2(acc2[p * TN + n], ap[p], bb[n]);
        }
        __syncthreads();
    }

#pragma unroll
    for (int p = 0; p < TMP; ++p) {
        int row0 = rowBase + ty * TM + 2 * p;
#pragma unroll
        for (int n4 = 0; n4 < TN / 4; ++n4) {
            int col = colBase + tx * TN + n4 * 4;
            float2 e0 = unpack2(acc2[p * TN + n4 * 4 + 0]);
            float2 e1 = unpack2(acc2[p * TN + n4 * 4 + 1]);
            float2 e2 = unpack2(acc2[p * TN + n4 * 4 + 2]);
            float2 e3 = unpack2(acc2[p * TN + n4 * 4 + 3]);
            float4 bv = *(const float4*)&bias[col];
            float4 v0, v1;
            v0.x = e0.x + bv.x; v0.y = e1.x + bv.y; v0.z = e2.x + bv.z; v0.w = e3.x + bv.w;
            v1.x = e0.y + bv.x; v1.y = e1.y + bv.y; v1.z = e2.y + bv.z; v1.w = e3.y + bv.w;
            if (RELU) {
                v0.x = fmaxf(v0.x, 0.f); v0.y = fmaxf(v0.y, 0.f);
                v0.z = fmaxf(v0.z, 0.f); v0.w = fmaxf(v0.w, 0.f);
                v1.x = fmaxf(v1.x, 0.f); v1.y = fmaxf(v1.y, 0.f);
                v1.z = fmaxf(v1.z, 0.f); v1.w = fmaxf(v1.w, 0.f);
            }
            if (!GUARD || row0 < NNODES)
                *(float4*)&C[(size_t)row0 * NCOLS + col] = v0;
            if (!GUARD || row0 + 1 < NNODES)
                *(float4*)&C[(size_t)(row0 + 1) * NCOLS + col] = v1;
        }
    }
}

// ---------------- BatchNorm --------------------------------------------------
__global__ void colstats_kernel(const float* __restrict__ X)
{
    int c = threadIdx.x;               // blockDim = 300, one column per thread
    int r0 = blockIdx.x * 250;
    int r1 = min(r0 + 250, NNODES);
    float s = 0.f, q = 0.f;
    for (int r = r0; r < r1; ++r) {
        float v = X[(size_t)r * DD + c];
        s += v;
        q = fmaf(v, v, q);
    }
    atomicAdd(&g_stats[c], s);
    atomicAdd(&g_stats[DD + c], q);
}

__global__ void bn_finalize_kernel(const float* __restrict__ gamma, const float* __restrict__ beta)
{
    int c = threadIdx.x;
    float inv_n = 1.f / (float)NNODES;
    float mean = g_stats[c] * inv_n;
    float var  = g_stats[DD + c] * inv_n - mean * mean;
    float sc = gamma[c] * rsqrtf(var + 1e-5f);
    g_ss[c] = sc;
    g_ss[DD + c] = beta[c] - mean * sc;
}

__global__ void bn_apply_kernel(float* __restrict__ X)
{
    const size_t n4 = (size_t)NNODES * (DD / 4);
    float4* p = (float4*)X;
    for (size_t i = (size_t)blockIdx.x * blockDim.x + threadIdx.x; i < n4;
         i += (size_t)gridDim.x * blockDim.x) {
        int c4 = (int)(i % (DD / 4)) * 4;
        float4 sc = *(const float4*)&g_ss[c4];
        float4 sh = *(const float4*)&g_ss[DD + c4];
        float4 x = p[i];
        x.x = fmaf(x.x, sc.x, sh.x);
        x.y = fmaf(x.y, sc.y, sh.y);
        x.z = fmaf(x.z, sc.z, sh.z);
        x.w = fmaf(x.w, sc.w, sh.w);
        p[i] = x;
    }
}

// ---------------- launch -----------------------------------------------------
extern "C" void kernel_launch(void* const* d_in, const int* in_sizes, int n_in,
                              void* d_out, int out_size)
{
    const float* node_feats = (const float*)d_in[0];
    const int*   src        = (const int*)d_in[1];
    const int*   dst        = (const int*)d_in[2];
    const int*   f0         = (const int*)d_in[3];
    const int*   f1         = (const int*)d_in[4];
    const float* emb_w0     = (const float*)d_in[5];
    const float* emb_b0     = (const float*)d_in[6];
    const float* emb_w1     = (const float*)d_in[7];
    const float* emb_b1     = (const float*)d_in[8];
    const float* w1         = (const float*)d_in[9];
    const float* b1         = (const float*)d_in[10];
    const float* w2         = (const float*)d_in[11];
    const float* b2         = (const float*)d_in[12];
    const float* gamma      = (const float*)d_in[13];
    const float* beta       = (const float*)d_in[14];
    float* out = (float*)d_out;

    float* agg; cudaGetSymbolAddress((void**)&agg, g_agg);
    float* h1;  cudaGetSymbolAddress((void**)&h1, g_h1);

    combo_init_kernel<<<19, 128>>>(emb_w0, emb_b0, emb_w1, emb_b1);
    zero_agg_kernel<<<2048, 256>>>();
    scatter_kernel<<<NE * 32 / 256, 256>>>(node_feats, src, dst, f0, f1);

    // GEMM1: (M_PAD x 300) * (300 x 600) + b1, ReLU -> g_h1
    sgemm_kernel<DD, DD2, 128, 120, 20, 8, 8, true, false>
        <<<dim3(DD2 / 120, M_PAD / 128), 240>>>(agg, w1, b1, h1);

    // GEMM2: (M_PAD x 600) * (600 x 300) + b2 -> out (guard rows >= NNODES)
    sgemm_kernel<DD2, DD, 128, 60, 20, 8, 4, false, true>
        <<<dim3(DD / 60, M_PAD / 128), 240>>>(h1, w2, b2, out);

    colstats_kernel<<<400, 300>>>(out);
    bn_finalize_kernel<<<1, 300>>>(gamma, beta);
    bn_apply_kernel<<<2048, 256>>>(out);
}

// round 6
// speedup vs baseline: 1.1404x; 1.0947x over previous
#include <cuda_runtime.h>
#include <cstddef>

#define NNODES 100000
#define NE     200000
#define DD     300
#define DD2    600
#define M_PAD  100096   // 128 * 782

// ---------------- scratch (static device globals; no runtime allocation) ----
__device__ float g_agg[(size_t)M_PAD * DD];     // aggregated messages (padded rows are zero)
__device__ float g_h1[(size_t)M_PAD * DD2];     // hidden after GEMM1+ReLU
__device__ float g_combo[18 * DD];              // all 6*3 edge-embedding rows (+biases)
__device__ float g_stats[2 * DD];               // per-column sum, sumsq
__device__ float g_ss[2 * DD];                  // per-column scale, shift

// ---------------- packed f32x2 helpers --------------------------------------
__device__ __forceinline__ void ffma2(unsigned long long& acc,
                                      unsigned long long a, unsigned long long b)
{
    asm("fma.rn.f32x2 %0, %1, %2, %0;" : "+l"(acc) : "l"(a), "l"(b));
}

__device__ __forceinline__ unsigned long long dup_f32(float v)
{
    unsigned long long r;
    unsigned int u = __float_as_uint(v);
    asm("mov.b64 %0, {%1, %1};" : "=l"(r) : "r"(u));
    return r;
}

__device__ __forceinline__ float2 unpack2(unsigned long long v)
{
    float2 r;
    asm("mov.b64 {%0, %1}, %2;" : "=f"(r.x), "=f"(r.y) : "l"(v));
    return r;
}

// ---------------- small init kernels ---------------------------------------
__global__ void combo_init_kernel(const float* __restrict__ w0, const float* __restrict__ b0,
                                  const float* __restrict__ w1, const float* __restrict__ b1)
{
    int b = blockIdx.x;
    if (b < 18) {
        int i0 = b / 3, i1 = b % 3;
        for (int d = threadIdx.x; d < DD; d += blockDim.x)
            g_combo[b * DD + d] = w0[i0 * DD + d] + b0[d] + w1[i1 * DD + d] + b1[d];
    } else {
        for (int d = threadIdx.x; d < 2 * DD; d += blockDim.x)
            g_stats[d] = 0.f;
    }
}

__global__ void zero_agg_kernel()
{
    const size_t n4 = (size_t)M_PAD * DD / 4;
    float4 z = make_float4(0.f, 0.f, 0.f, 0.f);
    float4* p = (float4*)g_agg;
    for (size_t i = (size_t)blockIdx.x * blockDim.x + threadIdx.x; i < n4;
         i += (size_t)gridDim.x * blockDim.x)
        p[i] = z;
}

// ---------------- edge scatter: agg[dst] += node_feats[src] + combo --------
__global__ void scatter_kernel(const float* __restrict__ nf, const int* __restrict__ src,
                               const int* __restrict__ dst, const int* __restrict__ f0,
                               const int* __restrict__ f1)
{
    int e = (blockIdx.x * blockDim.x + threadIdx.x) >> 5;  // one warp per edge
    int lane = threadIdx.x & 31;
    if (e >= NE) return;
    int s = __ldg(&src[e]);
    int t = __ldg(&dst[e]);
    int c = __ldg(&f0[e]) * 3 + __ldg(&f1[e]);
    const float4* nrow = (const float4*)(nf + (size_t)s * DD);
    const float4* crow = (const float4*)(g_combo + c * DD);
    float* orow = g_agg + (size_t)t * DD;
    for (int j = lane; j < DD / 4; j += 32) {
        float4 a = nrow[j];
        float4 b = crow[j];
        atomicAdd(orow + j * 4 + 0, a.x + b.x);
        atomicAdd(orow + j * 4 + 1, a.y + b.y);
        atomicAdd(orow + j * 4 + 2, a.z + b.z);
        atomicAdd(orow + j * 4 + 3, a.w + b.w);
    }
}

// ---------------- fp32 GEMM, packed FFMA2, conflict-free B fragments --------
// C[M_PAD, NCOLS] = A[M_PAD, KDIM] * B[KDIM, NCOLS] + bias, optional ReLU.
// B-column ownership is interleaved: thread tx owns float4 chunks at columns
// tx*4 + chunk*(TX*4)  ->  LDS.128 at tx*16B: consecutive lanes hit
// consecutive 16B lines = conflict-free shared loads (and coalesced stores).
template<int KDIM, int NCOLS, int BM, int BN, int BK, int TM, int TN, bool RELU, bool GUARD>
__global__ __launch_bounds__((BM / TM) * (BN / TN))
void sgemm_kernel(const float* __restrict__ A, const float* __restrict__ B,
                  const float* __restrict__ bias, float* __restrict__ C)
{
    constexpr int TX   = BN / TN;
    constexpr int TY   = BM / TM;
    constexpr int NT   = TX * TY;
    constexpr int AK4  = BK / 4;
    constexpr int BN4  = BN / 4;
    constexpr int TMP  = TM / 2;     // m-pairs
    constexpr int NCH  = TN / 4;     // B float4 chunks per thread

    __shared__ float As[BK][BM + 4]; // transposed A tile
    __shared__ float Bs[BK][BN];

    const int tid = threadIdx.x;
    const int tx = tid % TX;
    const int ty = tid / TX;
    const int rowBase = blockIdx.y * BM;
    const int colBase = blockIdx.x * BN;

    unsigned long long acc2[TMP * TN];
#pragma unroll
    for (int i = 0; i < TMP * TN; ++i) acc2[i] = 0ull;

    for (int kt = 0; kt < KDIM; kt += BK) {
        for (int idx = tid; idx < BM * AK4; idx += NT) {
            int row = idx / AK4;
            int k4  = idx % AK4;
            float4 v = *(const float4*)&A[(size_t)(rowBase + row) * KDIM + kt + k4 * 4];
            As[k4 * 4 + 0][row] = v.x;
            As[k4 * 4 + 1][row] = v.y;
            As[k4 * 4 + 2][row] = v.z;
            As[k4 * 4 + 3][row] = v.w;
        }
        for (int idx = tid; idx < BK * BN4; idx += NT) {
            int row = idx / BN4;
            int c4  = idx % BN4;
            *(float4*)&Bs[row][c4 * 4] =
                *(const float4*)&B[(size_t)(kt + row) * NCOLS + colBase + c4 * 4];
        }
        __syncthreads();

#pragma unroll
        for (int k = 0; k < BK; ++k) {
            float4 af[TM / 4], bf[NCH];
#pragma unroll
            for (int i = 0; i < TM / 4; ++i) af[i] = *(const float4*)&As[k][ty * TM + i * 4];
#pragma unroll
            for (int i = 0; i < NCH; ++i)
                bf[i] = *(const float4*)&Bs[k][tx * 4 + i * (TX * 4)];
            const unsigned long long* ap = (const unsigned long long*)af;  // (m, m+1) pairs
            const float* b = (const float*)bf;
            unsigned long long bb[TN];
#pragma unroll
            for (int n = 0; n < TN; ++n) bb[n] = dup_f32(b[n]);
#pragma unroll
            for (int p = 0; p < TMP; ++p)
#pragma unroll
                for (int n = 0; n < TN; ++n)
                    ffma2(acc2[p * TN + n], ap[p], bb[n]);
        }
        __syncthreads();
    }

#pragma unroll
    for (int p = 0; p < TMP; ++p) {
        int row0 = rowBase + ty * TM + 2 * p;
#pragma unroll
        for (int ch = 0; ch < NCH; ++ch) {
            int col = colBase + tx * 4 + ch * (TX * 4);
            float2 e0 = unpack2(acc2[p * TN + ch * 4 + 0]);
            float2 e1 = unpack2(acc2[p * TN + ch * 4 + 1]);
            float2 e2 = unpack2(acc2[p * TN + ch * 4 + 2]);
            float2 e3 = unpack2(acc2[p * TN + ch * 4 + 3]);
            float4 bv = *(const float4*)&bias[col];
            float4 v0, v1;
            v0.x = e0.x + bv.x; v0.y = e1.x + bv.y; v0.z = e2.x + bv.z; v0.w = e3.x + bv.w;
            v1.x = e0.y + bv.x; v1.y = e1.y + bv.y; v1.z = e2.y + bv.z; v1.w = e3.y + bv.w;
            if (RELU) {
                v0.x = fmaxf(v0.x, 0.f); v0.y = fmaxf(v0.y, 0.f);
                v0.z = fmaxf(v0.z, 0.f); v0.w = fmaxf(v0.w, 0.f);
                v1.x = fmaxf(v1.x, 0.f); v1.y = fmaxf(v1.y, 0.f);
                v1.z = fmaxf(v1.z, 0.f); v1.w = fmaxf(v1.w, 0.f);
            }
            if (!GUARD || row0 < NNODES)
                *(float4*)&C[(size_t)row0 * NCOLS + col] = v0;
            if (!GUARD || row0 + 1 < NNODES)
                *(float4*)&C[(size_t)(row0 + 1) * NCOLS + col] = v1;
        }
    }
}

// ---------------- BatchNorm --------------------------------------------------
__global__ void colstats_kernel(const float* __restrict__ X)
{
    int c = threadIdx.x;               // blockDim = 300, one column per thread
    int r0 = blockIdx.x * 250;
    int r1 = min(r0 + 250, NNODES);
    float s = 0.f, q = 0.f;
    for (int r = r0; r < r1; ++r) {
        float v = X[(size_t)r * DD + c];
        s += v;
        q = fmaf(v, v, q);
    }
    atomicAdd(&g_stats[c], s);
    atomicAdd(&g_stats[DD + c], q);
}

__global__ void bn_finalize_kernel(const float* __restrict__ gamma, const float* __restrict__ beta)
{
    int c = threadIdx.x;
    float inv_n = 1.f / (float)NNODES;
    float mean = g_stats[c] * inv_n;
    float var  = g_stats[DD + c] * inv_n - mean * mean;
    float sc = gamma[c] * rsqrtf(var + 1e-5f);
    g_ss[c] = sc;
    g_ss[DD + c] = beta[c] - mean * sc;
}

__global__ void bn_apply_kernel(float* __restrict__ X)
{
    const size_t n4 = (size_t)NNODES * (DD / 4);
    float4* p = (float4*)X;
    for (size_t i = (size_t)blockIdx.x * blockDim.x + threadIdx.x; i < n4;
         i += (size_t)gridDim.x * blockDim.x) {
        int c4 = (int)(i % (DD / 4)) * 4;
        float4 sc = *(const float4*)&g_ss[c4];
        float4 sh = *(const float4*)&g_ss[DD + c4];
        float4 x = p[i];
        x.x = fmaf(x.x, sc.x, sh.x);
        x.y = fmaf(x.y, sc.y, sh.y);
        x.z = fmaf(x.z, sc.z, sh.z);
        x.w = fmaf(x.w, sc.w, sh.w);
        p[i] = x;
    }
}

// ---------------- launch -----------------------------------------------------
extern "C" void kernel_launch(void* const* d_in, const int* in_sizes, int n_in,
                              void* d_out, int out_size)
{
    const float* node_feats = (const float*)d_in[0];
    const int*   src        = (const int*)d_in[1];
    const int*   dst        = (const int*)d_in[2];
    const int*   f0         = (const int*)d_in[3];
    const int*   f1         = (const int*)d_in[4];
    const float* emb_w0     = (const float*)d_in[5];
    const float* emb_b0     = (const float*)d_in[6];
    const float* emb_w1     = (const float*)d_in[7];
    const float* emb_b1     = (const float*)d_in[8];
    const float* w1         = (const float*)d_in[9];
    const float* b1         = (const float*)d_in[10];
    const float* w2         = (const float*)d_in[11];
    const float* b2         = (const float*)d_in[12];
    const float* gamma      = (const float*)d_in[13];
    const float* beta       = (const float*)d_in[14];
    float* out = (float*)d_out;

    float* agg; cudaGetSymbolAddress((void**)&agg, g_agg);
    float* h1;  cudaGetSymbolAddress((void**)&h1, g_h1);

    combo_init_kernel<<<19, 128>>>(emb_w0, emb_b0, emb_w1, emb_b1);
    zero_agg_kernel<<<2048, 256>>>();
    scatter_kernel<<<NE * 32 / 256, 256>>>(node_feats, src, dst, f0, f1);

    // GEMM1: (M_PAD x 300) * (300 x 600) + b1, ReLU -> g_h1
    sgemm_kernel<DD, DD2, 128, 120, 20, 8, 8, true, false>
        <<<dim3(DD2 / 120, M_PAD / 128), 240>>>(agg, w1, b1, h1);

    // GEMM2: (M_PAD x 600) * (600 x 300) + b2 -> out (guard rows >= NNODES)
    sgemm_kernel<DD2, DD, 128, 60, 20, 8, 4, false, true>
        <<<dim3(DD / 60, M_PAD / 128), 240>>>(h1, w2, b2, out);

    colstats_kernel<<<400, 300>>>(out);
    bn_finalize_kernel<<<1, 300>>>(gamma, beta);
    bn_apply_kernel<<<2048, 256>>>(out);
}

// round 7
// speedup vs baseline: 1.2090x; 1.0601x over previous
#include <cuda_runtime.h>
#include <cstddef>

#define NNODES 100000
#define NE     200000
#define DD     300
#define DD2    600
#define M_PAD  100096   // 128 * 782

// ---------------- scratch (static device globals; no runtime allocation) ----
__device__ float g_agg[(size_t)M_PAD * DD];     // aggregated messages (padded rows are zero)
__device__ float g_h1[(size_t)M_PAD * DD2];     // hidden after GEMM1+ReLU
__device__ float g_combo[18 * DD];              // all 6*3 edge-embedding rows (+biases)
__device__ float g_stats[2 * DD];               // per-column sum, sumsq
__device__ float g_ss[2 * DD];                  // per-column scale, shift

// ---------------- packed f32x2 helpers --------------------------------------
__device__ __forceinline__ void ffma2(unsigned long long& acc,
                                      unsigned long long a, unsigned long long b)
{
    asm("fma.rn.f32x2 %0, %1, %2, %0;" : "+l"(acc) : "l"(a), "l"(b));
}

__device__ __forceinline__ unsigned long long dup_f32(float v)
{
    unsigned long long r;
    unsigned int u = __float_as_uint(v);
    asm("mov.b64 %0, {%1, %1};" : "=l"(r) : "r"(u));
    return r;
}

__device__ __forceinline__ float2 unpack2(unsigned long long v)
{
    float2 r;
    asm("mov.b64 {%0, %1}, %2;" : "=f"(r.x), "=f"(r.y) : "l"(v));
    return r;
}

// ---------------- small init kernels ---------------------------------------
__global__ void combo_init_kernel(const float* __restrict__ w0, const float* __restrict__ b0,
                                  const float* __restrict__ w1, const float* __restrict__ b1)
{
    int b = blockIdx.x;
    if (b < 18) {
        int i0 = b / 3, i1 = b % 3;
        for (int d = threadIdx.x; d < DD; d += blockDim.x)
            g_combo[b * DD + d] = w0[i0 * DD + d] + b0[d] + w1[i1 * DD + d] + b1[d];
    } else {
        for (int d = threadIdx.x; d < 2 * DD; d += blockDim.x)
            g_stats[d] = 0.f;
    }
}

__global__ void zero_agg_kernel()
{
    const size_t n4 = (size_t)M_PAD * DD / 4;
    float4 z = make_float4(0.f, 0.f, 0.f, 0.f);
    float4* p = (float4*)g_agg;
    for (size_t i = (size_t)blockIdx.x * blockDim.x + threadIdx.x; i < n4;
         i += (size_t)gridDim.x * blockDim.x)
        p[i] = z;
}

// ---------------- edge scatter: agg[dst] += node_feats[src] + combo --------
__global__ void scatter_kernel(const float* __restrict__ nf, const int* __restrict__ src,
                               const int* __restrict__ dst, const int* __restrict__ f0,
                               const int* __restrict__ f1)
{
    int e = (blockIdx.x * blockDim.x + threadIdx.x) >> 5;  // one warp per edge
    int lane = threadIdx.x & 31;
    if (e >= NE) return;
    int s = __ldg(&src[e]);
    int t = __ldg(&dst[e]);
    int c = __ldg(&f0[e]) * 3 + __ldg(&f1[e]);
    const float4* nrow = (const float4*)(nf + (size_t)s * DD);
    const float4* crow = (const float4*)(g_combo + c * DD);
    float* orow = g_agg + (size_t)t * DD;
    for (int j = lane; j < DD / 4; j += 32) {
        float4 a = nrow[j];
        float4 b = crow[j];
        atomicAdd(orow + j * 4 + 0, a.x + b.x);
        atomicAdd(orow + j * 4 + 1, a.y + b.y);
        atomicAdd(orow + j * 4 + 2, a.z + b.z);
        atomicAdd(orow + j * 4 + 3, a.w + b.w);
    }
}

// ---------------- fp32 GEMM, FFMA2, double-buffered smem pipeline -----------
// C[M_PAD, NCOLS] = A[M_PAD, KDIM] * B[KDIM, NCOLS] + bias, optional ReLU.
// Per k-tile: issue next tile's LDGs into registers BEFORE the compute loop
// (compute ~640 issue-cycles hides the ~577-cyc DRAM latency), store to the
// alternate smem buffer after compute, single __syncthreads per tile.
template<int KDIM, int NCOLS, int BM, int BN, int BK, int TM, int TN, bool RELU, bool GUARD>
__global__ __launch_bounds__((BM / TM) * (BN / TN), 2)
void sgemm_kernel(const float* __restrict__ A, const float* __restrict__ B,
                  const float* __restrict__ bias, float* __restrict__ C)
{
    constexpr int TX   = BN / TN;
    constexpr int TY   = BM / TM;
    constexpr int NT   = TX * TY;
    constexpr int AK4  = BK / 4;
    constexpr int BN4  = BN / 4;
    constexpr int TMP  = TM / 2;                 // m-pairs
    constexpr int NCH  = TN / 4;                 // B float4 chunks per thread
    constexpr int A4T  = BM * AK4;               // float4s in A tile
    constexpr int B4T  = BK * BN4;               // float4s in B tile
    constexpr int AIT  = (A4T + NT - 1) / NT;
    constexpr int BIT  = (B4T + NT - 1) / NT;
    constexpr int NKT  = KDIM / BK;

    __shared__ float As[2][BK][BM + 4];          // transposed A tiles
    __shared__ float Bs[2][BK][BN];

    const int tid = threadIdx.x;
    const int tx = tid % TX;
    const int ty = tid / TX;
    const int rowBase = blockIdx.y * BM;
    const int colBase = blockIdx.x * BN;

    float4 pa[AIT], pb[BIT];

    auto ldg_tile = [&](int kt) {
#pragma unroll
        for (int i = 0; i < AIT; ++i) {
            int idx = tid + i * NT;
            if (idx < A4T) {
                int row = idx / AK4, k4 = idx % AK4;
                pa[i] = *(const float4*)&A[(size_t)(rowBase + row) * KDIM + kt + k4 * 4];
            }
        }
#pragma unroll
        for (int i = 0; i < BIT; ++i) {
            int idx = tid + i * NT;
            if (idx < B4T) {
                int row = idx / BN4, c4 = idx % BN4;
                pb[i] = *(const float4*)&B[(size_t)(kt + row) * NCOLS + colBase + c4 * 4];
            }
        }
    };
    auto sts_tile = [&](int buf) {
#pragma unroll
        for (int i = 0; i < AIT; ++i) {
            int idx = tid + i * NT;
            if (idx < A4T) {
                int row = idx / AK4, k4 = idx % AK4;
                As[buf][k4 * 4 + 0][row] = pa[i].x;
                As[buf][k4 * 4 + 1][row] = pa[i].y;
                As[buf][k4 * 4 + 2][row] = pa[i].z;
                As[buf][k4 * 4 + 3][row] = pa[i].w;
            }
        }
#pragma unroll
        for (int i = 0; i < BIT; ++i) {
            int idx = tid + i * NT;
            if (idx < B4T) {
                int row = idx / BN4, c4 = idx % BN4;
                *(float4*)&Bs[buf][row][c4 * 4] = pb[i];
            }
        }
    };

    unsigned long long acc2[TMP * TN];
#pragma unroll
    for (int i = 0; i < TMP * TN; ++i) acc2[i] = 0ull;

    ldg_tile(0);
    sts_tile(0);
    __syncthreads();

    for (int t = 0; t < NKT; ++t) {
        int buf = t & 1;
        if (t + 1 < NKT) ldg_tile((t + 1) * BK);

#pragma unroll
        for (int k = 0; k < BK; ++k) {
            float4 af[TM / 4], bf[NCH];
#pragma unroll
            for (int i = 0; i < TM / 4; ++i)
                af[i] = *(const float4*)&As[buf][k][ty * TM + i * 4];
#pragma unroll
            for (int i = 0; i < NCH; ++i)
                bf[i] = *(const float4*)&Bs[buf][k][tx * 4 + i * (TX * 4)];
            const unsigned long long* ap = (const unsigned long long*)af;  // (m, m+1) pairs
            const float* b = (const float*)bf;
            unsigned long long bb[TN];
#pragma unroll
            for (int n = 0; n < TN; ++n) bb[n] = dup_f32(b[n]);
#pragma unroll
            for (int p = 0; p < TMP; ++p)
#pragma unroll
                for (int n = 0; n < TN; ++n)
                    ffma2(acc2[p * TN + n], ap[p], bb[n]);
        }

        if (t + 1 < NKT) {
            sts_tile(buf ^ 1);   // safe: last readers of buf^1 drained at end of iter t-1
            __syncthreads();
        }
    }

#pragma unroll
    for (int p = 0; p < TMP; ++p) {
        int row0 = rowBase + ty * TM + 2 * p;
#pragma unroll
        for (int ch = 0; ch < NCH; ++ch) {
            int col = colBase + tx * 4 + ch * (TX * 4);
            float2 e0 = unpack2(acc2[p * TN + ch * 4 + 0]);
            float2 e1 = unpack2(acc2[p * TN + ch * 4 + 1]);
            float2 e2 = unpack2(acc2[p * TN + ch * 4 + 2]);
            float2 e3 = unpack2(acc2[p * TN + ch * 4 + 3]);
            float4 bv = *(const float4*)&bias[col];
            float4 v0, v1;
            v0.x = e0.x + bv.x; v0.y = e1.x + bv.y; v0.z = e2.x + bv.z; v0.w = e3.x + bv.w;
            v1.x = e0.y + bv.x; v1.y = e1.y + bv.y; v1.z = e2.y + bv.z; v1.w = e3.y + bv.w;
            if (RELU) {
                v0.x = fmaxf(v0.x, 0.f); v0.y = fmaxf(v0.y, 0.f);
                v0.z = fmaxf(v0.z, 0.f); v0.w = fmaxf(v0.w, 0.f);
                v1.x = fmaxf(v1.x, 0.f); v1.y = fmaxf(v1.y, 0.f);
                v1.z = fmaxf(v1.z, 0.f); v1.w = fmaxf(v1.w, 0.f);
            }
            if (!GUARD || row0 < NNODES)
                *(float4*)&C[(size_t)row0 * NCOLS + col] = v0;
            if (!GUARD || row0 + 1 < NNODES)
                *(float4*)&C[(size_t)(row0 + 1) * NCOLS + col] = v1;
        }
    }
}

// ---------------- BatchNorm --------------------------------------------------
__global__ void colstats_kernel(const float* __restrict__ X)
{
    int c = threadIdx.x;               // blockDim = 300, one column per thread
    int r0 = blockIdx.x * 250;
    int r1 = min(r0 + 250, NNODES);
    float s = 0.f, q = 0.f;
    for (int r = r0; r < r1; ++r) {
        float v = X[(size_t)r * DD + c];
        s += v;
        q = fmaf(v, v, q);
    }
    atomicAdd(&g_stats[c], s);
    atomicAdd(&g_stats[DD + c], q);
}

__global__ void bn_finalize_kernel(const float* __restrict__ gamma, const float* __restrict__ beta)
{
    int c = threadIdx.x;
    float inv_n = 1.f / (float)NNODES;
    float mean = g_stats[c] * inv_n;
    float var  = g_stats[DD + c] * inv_n - mean * mean;
    float sc = gamma[c] * rsqrtf(var + 1e-5f);
    g_ss[c] = sc;
    g_ss[DD + c] = beta[c] - mean * sc;
}

__global__ void bn_apply_kernel(float* __restrict__ X)
{
    const size_t n4 = (size_t)NNODES * (DD / 4);
    float4* p = (float4*)X;
    for (size_t i = (size_t)blockIdx.x * blockDim.x + threadIdx.x; i < n4;
         i += (size_t)gridDim.x * blockDim.x) {
        int c4 = (int)(i % (DD / 4)) * 4;
        float4 sc = *(const float4*)&g_ss[c4];
        float4 sh = *(const float4*)&g_ss[DD + c4];
        float4 x = p[i];
        x.x = fmaf(x.x, sc.x, sh.x);
        x.y = fmaf(x.y, sc.y, sh.y);
        x.z = fmaf(x.z, sc.z, sh.z);
        x.w = fmaf(x.w, sc.w, sh.w);
        p[i] = x;
    }
}

// ---------------- launch -----------------------------------------------------
extern "C" void kernel_launch(void* const* d_in, const int* in_sizes, int n_in,
                              void* d_out, int out_size)
{
    const float* node_feats = (const float*)d_in[0];
    const int*   src        = (const int*)d_in[1];
    const int*   dst        = (const int*)d_in[2];
    const int*   f0         = (const int*)d_in[3];
    const int*   f1         = (const int*)d_in[4];
    const float* emb_w0     = (const float*)d_in[5];
    const float* emb_b0     = (const float*)d_in[6];
    const float* emb_w1     = (const float*)d_in[7];
    const float* emb_b1     = (const float*)d_in[8];
    const float* w1         = (const float*)d_in[9];
    const float* b1         = (const float*)d_in[10];
    const float* w2         = (const float*)d_in[11];
    const float* b2         = (const float*)d_in[12];
    const float* gamma      = (const float*)d_in[13];
    const float* beta       = (const float*)d_in[14];
    float* out = (float*)d_out;

    float* agg; cudaGetSymbolAddress((void**)&agg, g_agg);
    float* h1;  cudaGetSymbolAddress((void**)&h1, g_h1);

    combo_init_kernel<<<19, 128>>>(emb_w0, emb_b0, emb_w1, emb_b1);
    zero_agg_kernel<<<2048, 256>>>();
    scatter_kernel<<<NE * 32 / 256, 256>>>(node_feats, src, dst, f0, f1);

    // GEMM1: (M_PAD x 300) * (300 x 600) + b1, ReLU -> g_h1
    sgemm_kernel<DD, DD2, 128, 120, 20, 8, 8, true, false>
        <<<dim3(DD2 / 120, M_PAD / 128), 240>>>(agg, w1, b1, h1);

    // GEMM2: (M_PAD x 600) * (600 x 300) + b2 -> out (guard rows >= NNODES)
    sgemm_kernel<DD2, DD, 128, 60, 20, 8, 4, false, true>
        <<<dim3(DD / 60, M_PAD / 128), 240>>>(h1, w2, b2, out);

    colstats_kernel<<<400, 300>>>(out);
    bn_finalize_kernel<<<1, 300>>>(gamma, beta);
    bn_apply_kernel<<<2048, 256>>>(out);
}

// round 12
// speedup vs baseline: 2.2071x; 1.8256x over previous
#include <cuda_runtime.h>
#include <cuda_bf16.h>
#include <cstdint>
#include <cstddef>

#define NNODES 100000
#define NE     200000
#define DD     300
#define DD2    600
#define M_PAD  100096   // 128 * 782

// GEMM1: A[M,300] * w1 -> h1[M,600];  K padded 320, N padded 640
// GEMM2: h1[M,600] * w2 -> out[M,300]; K padded 640, N padded 384
#define KP1 320
#define NP1 640
#define KP2 640
#define NP2 384

// ---------------- scratch (static device globals; no runtime allocation) ----
__device__ float g_agg[(size_t)M_PAD * DD];
__device__ __nv_bfloat16 g_a1h[(size_t)M_PAD * KP1];   // agg split hi
__device__ __nv_bfloat16 g_a1l[(size_t)M_PAD * KP1];   // agg split lo
__device__ __nv_bfloat16 g_h1h[(size_t)M_PAD * KP2];   // h1 split hi (KP2 == NP1)
__device__ __nv_bfloat16 g_h1l[(size_t)M_PAD * KP2];   // h1 split lo
__device__ __nv_bfloat16 g_bt1h[NP1 * KP1], g_bt1l[NP1 * KP1];  // w1^T split
__device__ __nv_bfloat16 g_bt2h[NP2 * KP2], g_bt2l[NP2 * KP2];  // w2^T split
__device__ float g_combo[18 * DD];
__device__ float g_stats[2 * DD];
__device__ float g_ss[2 * DD];

// ---------------- PTX helpers (baseline ISA only: ldmatrix + mma.sync) ------
__device__ __forceinline__ uint32_t smem_u32(const void* p)
{
    uint32_t a;
    asm("{ .reg .u64 t; cvta.to.shared.u64 t, %1; cvt.u32.u64 %0, t; }" : "=r"(a) : "l"(p));
    return a;
}

__device__ __forceinline__ void ldsm4(uint32_t r[4], uint32_t addr)
{
    asm volatile("ldmatrix.sync.aligned.m8n8.x4.shared.b16 {%0,%1,%2,%3}, [%4];"
                 : "=r"(r[0]), "=r"(r[1]), "=r"(r[2]), "=r"(r[3]) : "r"(addr));
}

__device__ __forceinline__ void mma16816(float c[4], const uint32_t a[4],
                                         uint32_t b0, uint32_t b1)
{
    asm volatile(
        "mma.sync.aligned.m16n8k16.row.col.f32.bf16.bf16.f32 "
        "{%0,%1,%2,%3}, {%4,%5,%6,%7}, {%8,%9}, {%0,%1,%2,%3};"
        : "+f"(c[0]), "+f"(c[1]), "+f"(c[2]), "+f"(c[3])
        : "r"(a[0]), "r"(a[1]), "r"(a[2]), "r"(a[3]), "r"(b0), "r"(b1));
}

__device__ __forceinline__ uint32_t pack2h(__nv_bfloat16 a, __nv_bfloat16 b)
{
    return (uint32_t)__bfloat16_as_ushort(a) | ((uint32_t)__bfloat16_as_ushort(b) << 16);
}

// smem tile: 128 rows x 32 bf16, row stride 80 bytes (64 data + 16 pad:
// 16B-aligned rows, 8-row ldmatrix phases hit 8 distinct bank groups)
#define SROW 80

// ---------------- small init kernels ---------------------------------------
__global__ void combo_init_kernel(const float* __restrict__ w0, const float* __restrict__ b0,
                                  const float* __restrict__ w1, const float* __restrict__ b1)
{
    int b = blockIdx.x;
    if (b < 18) {
        int i0 = b / 3, i1 = b % 3;
        for (int d = threadIdx.x; d < DD; d += blockDim.x)
            g_combo[b * DD + d] = w0[i0 * DD + d] + b0[d] + w1[i1 * DD + d] + b1[d];
    } else {
        for (int d = threadIdx.x; d < 2 * DD; d += blockDim.x)
            g_stats[d] = 0.f;
    }
}

__global__ void zero_agg_kernel()
{
    const size_t n4 = (size_t)M_PAD * DD / 4;
    float4 z = make_float4(0.f, 0.f, 0.f, 0.f);
    float4* p = (float4*)g_agg;
    for (size_t i = (size_t)blockIdx.x * blockDim.x + threadIdx.x; i < n4;
         i += (size_t)gridDim.x * blockDim.x)
        p[i] = z;
}

// transpose + bf16-split the MLP weights (B^T, zero-padded)
__global__ void split_w1_kernel(const float* __restrict__ w1)
{
    int idx = blockIdx.x * blockDim.x + threadIdx.x;
    if (idx >= NP1 * KP1) return;
    int n = idx / KP1, k = idx % KP1;
    float v = (n < DD2 && k < DD) ? w1[(size_t)k * DD2 + n] : 0.f;
    __nv_bfloat16 h = __float2bfloat16_rn(v);
    g_bt1h[idx] = h;
    g_bt1l[idx] = __float2bfloat16_rn(v - __bfloat162float(h));
}

__global__ void split_w2_kernel(const float* __restrict__ w2)
{
    int idx = blockIdx.x * blockDim.x + threadIdx.x;
    if (idx >= NP2 * KP2) return;
    int n = idx / KP2, k = idx % KP2;
    float v = (n < DD && k < DD2) ? w2[(size_t)k * DD + n] : 0.f;
    __nv_bfloat16 h = __float2bfloat16_rn(v);
    g_bt2h[idx] = h;
    g_bt2l[idx] = __float2bfloat16_rn(v - __bfloat162float(h));
}

// split agg fp32 -> bf16 hi/lo, zero-padded K to KP1
__global__ void split_a_kernel()
{
    size_t idx = (size_t)blockIdx.x * blockDim.x + threadIdx.x;
    const size_t total = (size_t)M_PAD * KP1;
    if (idx >= total) return;
    int k = (int)(idx % KP1);
    size_t row = idx / KP1;
    float v = (k < DD) ? g_agg[row * DD + k] : 0.f;
    __nv_bfloat16 h = __float2bfloat16_rn(v);
    g_a1h[idx] = h;
    g_a1l[idx] = __float2bfloat16_rn(v - __bfloat162float(h));
}

// ---------------- edge scatter ----------------------------------------------
__global__ void scatter_kernel(const float* __restrict__ nf, const int* __restrict__ src,
                               const int* __restrict__ dst, const int* __restrict__ f0,
                               const int* __restrict__ f1)
{
    int e = (blockIdx.x * blockDim.x + threadIdx.x) >> 5;
    int lane = threadIdx.x & 31;
    if (e >= NE) return;
    int s = __ldg(&src[e]);
    int t = __ldg(&dst[e]);
    int c = __ldg(&f0[e]) * 3 + __ldg(&f1[e]);
    const float4* nrow = (const float4*)(nf + (size_t)s * DD);
    const float4* crow = (const float4*)(g_combo + c * DD);
    float* orow = g_agg + (size_t)t * DD;
    for (int j = lane; j < DD / 4; j += 32) {
        float4 a = nrow[j];
        float4 b = crow[j];
        atomicAdd(orow + j * 4 + 0, a.x + b.x);
        atomicAdd(orow + j * 4 + 1, a.y + b.y);
        atomicAdd(orow + j * 4 + 2, a.z + b.z);
        atomicAdd(orow + j * 4 + 3, a.w + b.w);
    }
}

// ---------------- mma.sync bf16-split GEMM core -----------------------------
// CTA 128x128, 8 warps (4m x 2n), warp tile 32x64. 3 products:
// Ah*Bh + Ah*Bl + Al*Bh, fp32 accumulate (HMMA).
#define GEMM_MAIN(Ah_, Al_, Bh_, Bl_, KP_)                                          \
    __shared__ __align__(16) char sAh[128 * SROW], sAl[128 * SROW];                 \
    __shared__ __align__(16) char sBh[128 * SROW], sBl[128 * SROW];                 \
    const int tid = threadIdx.x, wid = tid >> 5, lane = tid & 31;                   \
    const int warp_m = wid & 3, warp_n = wid >> 2;                                  \
    const int nbase = blockIdx.x * 128;                                             \
    const int mbase = blockIdx.y * 128;                                             \
    const uint32_t uAh = smem_u32(sAh), uAl = smem_u32(sAl);                        \
    const uint32_t uBh = smem_u32(sBh), uBl = smem_u32(sBl);                        \
    float acc[2][8][4];                                                             \
    _Pragma("unroll") for (int i = 0; i < 2; ++i)                                   \
    _Pragma("unroll") for (int j = 0; j < 8; ++j)                                   \
    _Pragma("unroll") for (int q = 0; q < 4; ++q) acc[i][j][q] = 0.f;               \
    for (int kt = 0; kt < (KP_) / 32; ++kt) {                                       \
        _Pragma("unroll") for (int i = 0; i < 2; ++i) {                             \
            int idx = tid + i * 256;                                                \
            int row = idx >> 2, c16 = idx & 3;                                      \
            const uint4* pa_h = (const uint4*)((Ah_) + (size_t)(mbase + row) * (KP_)) + kt * 4 + c16; \
            const uint4* pa_l = (const uint4*)((Al_) + (size_t)(mbase + row) * (KP_)) + kt * 4 + c16; \
            const uint4* pb_h = (const uint4*)((Bh_) + (size_t)(nbase + row) * (KP_)) + kt * 4 + c16; \
            const uint4* pb_l = (const uint4*)((Bl_) + (size_t)(nbase + row) * (KP_)) + kt * 4 + c16; \
            *(uint4*)(sAh + row * SROW + c16 * 16) = *pa_h;                         \
            *(uint4*)(sAl + row * SROW + c16 * 16) = *pa_l;                         \
            *(uint4*)(sBh + row * SROW + c16 * 16) = *pb_h;                         \
            *(uint4*)(sBl + row * SROW + c16 * 16) = *pb_l;                         \
        }                                                                           \
        __syncthreads();                                                            \
        _Pragma("unroll") for (int kk = 0; kk < 2; ++kk) {                          \
            const int kb = kk * 32;                                                 \
            uint32_t ah[2][4], al[2][4];                                            \
            _Pragma("unroll") for (int mi = 0; mi < 2; ++mi) {                      \
                uint32_t ra = (uint32_t)((warp_m * 32 + mi * 16 + (lane & 15)) * SROW \
                                         + kb + ((lane >> 4) << 4));                \
                ldsm4(ah[mi], uAh + ra);                                            \
                ldsm4(al[mi], uAl + ra);                                            \
            }                                                                       \
            _Pragma("unroll") for (int g = 0; g < 4; ++g) {                         \
                uint32_t bh[4], bl[4];                                              \
                uint32_t rb = (uint32_t)((warp_n * 64 + g * 16 + (lane & 7)         \
                                          + ((lane >> 4) << 3)) * SROW              \
                                         + kb + (((lane >> 3) & 1) << 4));          \
                ldsm4(bh, uBh + rb);                                                \
                ldsm4(bl, uBl + rb);                                                \
                _Pragma("unroll") for (int mi = 0; mi < 2; ++mi)                    \
                _Pragma("unroll") for (int h = 0; h < 2; ++h) {                     \
                    mma16816(acc[mi][g * 2 + h], ah[mi], bh[2 * h], bh[2 * h + 1]); \
                    mma16816(acc[mi][g * 2 + h], ah[mi], bl[2 * h], bl[2 * h + 1]); \
                    mma16816(acc[mi][g * 2 + h], al[mi], bh[2 * h], bh[2 * h + 1]); \
                }                                                                   \
            }                                                                       \
        }                                                                           \
        __syncthreads();                                                            \
    }

// GEMM1: + bias, ReLU, output split to bf16 hi/lo (padded cols -> 0)
__global__ void __launch_bounds__(256, 2) gemm1_mma(
    const __nv_bfloat16* __restrict__ Ah, const __nv_bfloat16* __restrict__ Al,
    const __nv_bfloat16* __restrict__ Bh, const __nv_bfloat16* __restrict__ Bl,
    const float* __restrict__ bias,
    __nv_bfloat16* __restrict__ Ch, __nv_bfloat16* __restrict__ Cl)
{
    GEMM_MAIN(Ah, Al, Bh, Bl, KP1)

#pragma unroll
    for (int mi = 0; mi < 2; ++mi) {
        int row0 = mbase + warp_m * 32 + mi * 16 + (lane >> 2);
#pragma unroll
        for (int n8 = 0; n8 < 8; ++n8) {
            int col = nbase + warp_n * 64 + n8 * 8 + 2 * (lane & 3);
#pragma unroll
            for (int rr = 0; rr < 2; ++rr) {
                int row = row0 + rr * 8;
                uint32_t hv = 0, lv = 0;
                if (col < DD2) {
                    float2 bb = *(const float2*)&bias[col];
                    float v0 = fmaxf(acc[mi][n8][2 * rr] + bb.x, 0.f);
                    float v1 = fmaxf(acc[mi][n8][2 * rr + 1] + bb.y, 0.f);
                    __nv_bfloat16 h0 = __float2bfloat16_rn(v0);
                    __nv_bfloat16 h1 = __float2bfloat16_rn(v1);
                    hv = pack2h(h0, h1);
                    lv = pack2h(__float2bfloat16_rn(v0 - __bfloat162float(h0)),
                                __float2bfloat16_rn(v1 - __bfloat162float(h1)));
                }
                *(uint32_t*)(Ch + (size_t)row * NP1 + col) = hv;
                *(uint32_t*)(Cl + (size_t)row * NP1 + col) = lv;
            }
        }
    }
}

// GEMM2: + bias, fp32 out with row/col guards
__global__ void __launch_bounds__(256, 2) gemm2_mma(
    const __nv_bfloat16* __restrict__ Ah, const __nv_bfloat16* __restrict__ Al,
    const __nv_bfloat16* __restrict__ Bh, const __nv_bfloat16* __restrict__ Bl,
    const float* __restrict__ bias, float* __restrict__ C)
{
    GEMM_MAIN(Ah, Al, Bh, Bl, KP2)

#pragma unroll
    for (int mi = 0; mi < 2; ++mi) {
        int row0 = mbase + warp_m * 32 + mi * 16 + (lane >> 2);
#pragma unroll
        for (int n8 = 0; n8 < 8; ++n8) {
            int col = nbase + warp_n * 64 + n8 * 8 + 2 * (lane & 3);
            if (col >= DD) continue;
            float2 bb = *(const float2*)&bias[col];
#pragma unroll
            for (int rr = 0; rr < 2; ++rr) {
                int row = row0 + rr * 8;
                if (row < NNODES) {
                    float2 v;
                    v.x = acc[mi][n8][2 * rr] + bb.x;
                    v.y = acc[mi][n8][2 * rr + 1] + bb.y;
                    *(float2*)(C + (size_t)row * DD + col) = v;
                }
            }
        }
    }
}

// ---------------- BatchNorm --------------------------------------------------
__global__ void colstats_kernel(const float* __restrict__ X)
{
    int c = threadIdx.x;
    int r0 = blockIdx.x * 250;
    int r1 = min(r0 + 250, NNODES);
    float s = 0.f, q = 0.f;
    for (int r = r0; r < r1; ++r) {
        float v = X[(size_t)r * DD + c];
        s += v;
        q = fmaf(v, v, q);
    }
    atomicAdd(&g_stats[c], s);
    atomicAdd(&g_stats[DD + c], q);
}

__global__ void bn_finalize_kernel(const float* __restrict__ gamma, const float* __restrict__ beta)
{
    int c = threadIdx.x;
    float inv_n = 1.f / (float)NNODES;
    float mean = g_stats[c] * inv_n;
    float var  = g_stats[DD + c] * inv_n - mean * mean;
    float sc = gamma[c] * rsqrtf(var + 1e-5f);
    g_ss[c] = sc;
    g_ss[DD + c] = beta[c] - mean * sc;
}

__global__ void bn_apply_kernel(float* __restrict__ X)
{
    const size_t n4 = (size_t)NNODES * (DD / 4);
    float4* p = (float4*)X;
    for (size_t i = (size_t)blockIdx.x * blockDim.x + threadIdx.x; i < n4;
         i += (size_t)gridDim.x * blockDim.x) {
        int c4 = (int)(i % (DD / 4)) * 4;
        float4 sc = *(const float4*)&g_ss[c4];
        float4 sh = *(const float4*)&g_ss[DD + c4];
        float4 x = p[i];
        x.x = fmaf(x.x, sc.x, sh.x);
        x.y = fmaf(x.y, sc.y, sh.y);
        x.z = fmaf(x.z, sc.z, sh.z);
        x.w = fmaf(x.w, sc.w, sh.w);
        p[i] = x;
    }
}

// ---------------- launch -----------------------------------------------------
extern "C" void kernel_launch(void* const* d_in, const int* in_sizes, int n_in,
                              void* d_out, int out_size)
{
    const float* node_feats = (const float*)d_in[0];
    const int*   src        = (const int*)d_in[1];
    const int*   dst        = (const int*)d_in[2];
    const int*   f0         = (const int*)d_in[3];
    const int*   f1         = (const int*)d_in[4];
    const float* emb_w0     = (const float*)d_in[5];
    const float* emb_b0     = (const float*)d_in[6];
    const float* emb_w1     = (const float*)d_in[7];
    const float* emb_b1     = (const float*)d_in[8];
    const float* w1         = (const float*)d_in[9];
    const float* b1         = (const float*)d_in[10];
    const float* w2         = (const float*)d_in[11];
    const float* b2         = (const float*)d_in[12];
    const float* gamma      = (const float*)d_in[13];
    const float* beta       = (const float*)d_in[14];
    float* out = (float*)d_out;

    __nv_bfloat16 *a1h, *a1l, *h1h, *h1l, *bt1h, *bt1l, *bt2h, *bt2l;
    cudaGetSymbolAddress((void**)&a1h, g_a1h);
    cudaGetSymbolAddress((void**)&a1l, g_a1l);
    cudaGetSymbolAddress((void**)&h1h, g_h1h);
    cudaGetSymbolAddress((void**)&h1l, g_h1l);
    cudaGetSymbolAddress((void**)&bt1h, g_bt1h);
    cudaGetSymbolAddress((void**)&bt1l, g_bt1l);
    cudaGetSymbolAddress((void**)&bt2h, g_bt2h);
    cudaGetSymbolAddress((void**)&bt2l, g_bt2l);

    combo_init_kernel<<<19, 128>>>(emb_w0, emb_b0, emb_w1, emb_b1);
    zero_agg_kernel<<<2048, 256>>>();
    split_w1_kernel<<<(NP1 * KP1 + 255) / 256, 256>>>(w1);
    split_w2_kernel<<<(NP2 * KP2 + 255) / 256, 256>>>(w2);
    scatter_kernel<<<NE * 32 / 256, 256>>>(node_feats, src, dst, f0, f1);

    // split aggregated messages into bf16 hi/lo (after scatter)
    {
        size_t total = (size_t)M_PAD * KP1;
        split_a_kernel<<<(unsigned)((total + 255) / 256), 256>>>();
    }

    gemm1_mma<<<dim3(NP1 / 128, M_PAD / 128), 256>>>(a1h, a1l, bt1h, bt1l, b1, h1h, h1l);
    gemm2_mma<<<dim3(NP2 / 128, M_PAD / 128), 256>>>(h1h, h1l, bt2h, bt2l, b2, out);

    colstats_kernel<<<400, 300>>>(out);
    bn_finalize_kernel<<<1, 300>>>(gamma, beta);
    bn_apply_kernel<<<2048, 256>>>(out);
}